// round 13
// baseline (speedup 1.0000x reference)
#include <cuda_runtime.h>
#include <cuda_bf16.h>
#include <math.h>
#include <stdint.h>

// Problem constants
#define BB   64
#define TT   512
#define EE   128
#define HH   256
#define HP   128
#define KK   32
#define SOS  2
#define EOS  3

// LSTM recurrence split: KS h-slices of wh in smem (bf16), TAILK in registers (fp32)
#define KS    48
#define TAILK 80
#define LSTM_SMEM (KS*512*2 + (512 + 256) * 4)

// GEMM tile smem: two 64x128 tiles padded to 132 words/row
#define GEMM_SMEM (2 * 64 * 132 * 4)

typedef unsigned long long ull;

__device__ __forceinline__ ull fma2(ull a, ull b, ull c) {
    ull d;
    asm("fma.rn.f32x2 %0, %1, %2, %3;" : "=l"(d) : "l"(a), "l"(b), "l"(c));
    return d;
}
__device__ __forceinline__ ull add2(ull a, ull b) {
    ull d;
    asm("add.rn.f32x2 %0, %1, %2;" : "=l"(d) : "l"(a), "l"(b));
    return d;
}
__device__ __forceinline__ float2 unpack2(ull a) {
    float2 r;
    asm("mov.b64 {%0, %1}, %2;" : "=f"(r.x), "=f"(r.y) : "l"(a));
    return r;
}
// packed (bf16 lo, bf16 hi) -> f32x2 pair (exact: bf16 is top 16 bits of f32)
__device__ __forceinline__ ull bf2up(uint32_t r) {
    ull d;
    asm("{ .reg .b32 lo, hi;\n\t"
        "  shl.b32 lo, %1, 16;\n\t"
        "  and.b32 hi, %1, 0xFFFF0000;\n\t"
        "  mov.b64 %0, {lo, hi}; }"
        : "=l"(d) : "r"(r));
    return d;
}
__device__ __forceinline__ uint32_t tf32cvt(float x) {
    uint32_t u;
    asm("cvt.rna.tf32.f32 %0, %1;" : "=r"(u) : "f"(x));
    return u;
}
__device__ __forceinline__ void mma_tf32(float c[4],
                                         uint32_t a0, uint32_t a1, uint32_t a2, uint32_t a3,
                                         uint32_t b0, uint32_t b1) {
    asm("mma.sync.aligned.m16n8k8.row.col.f32.tf32.tf32.f32 "
        "{%0,%1,%2,%3},{%4,%5,%6,%7},{%8,%9},{%0,%1,%2,%3};"
        : "+f"(c[0]), "+f"(c[1]), "+f"(c[2]), "+f"(c[3])
        : "r"(a0), "r"(a1), "r"(a2), "r"(a3), "r"(b0), "r"(b1));
}

// ---------------- device scratch ----------------
__device__ float g_G [ (size_t)BB * TT * 1024 ];   // gate preactivations, both dirs
__device__ float g_H0[ (size_t)BB * TT * 256 ];
__device__ float g_H1[ (size_t)BB * TT * 256 ];
__device__ float g_E [ (size_t)BB * TT * 32 ];
__device__ float g_whT[ 4 * 128 * 512 ];           // [dl][k][512]
__device__ float g_wi0[ 1024 * 128 ];
__device__ float g_wi1[ 1024 * 256 ];
__device__ float g_b0 [ 1024 ];
__device__ float g_b1 [ 1024 ];
__device__ int   g_len[ BB ];

// ---------------- prep: lengths + all weight packing in one launch ----------------
__global__ void prep_kernel(const int* __restrict__ x,
                            const float* __restrict__ wi0f, const float* __restrict__ wi0b,
                            const float* __restrict__ b0f,  const float* __restrict__ b0b,
                            const float* __restrict__ wi1f, const float* __restrict__ wi1b,
                            const float* __restrict__ b1f,  const float* __restrict__ b1b,
                            const float* __restrict__ wh0f, const float* __restrict__ wh0b,
                            const float* __restrict__ wh1f, const float* __restrict__ wh1b)
{
    if (blockIdx.x < BB) {
        int b = blockIdx.x;
        __shared__ int cnt;
        if (threadIdx.x == 0) cnt = 0;
        __syncthreads();
        int local = 0;
        for (int t = threadIdx.x; t < TT; t += blockDim.x)
            local += (x[b * TT + t] > 0) ? 1 : 0;
        atomicAdd(&cnt, local);
        __syncthreads();
        if (threadIdx.x == 0) g_len[b] = cnt;
        return;
    }

    int tid = (blockIdx.x - BB) * blockDim.x + threadIdx.x;
    int stride = (gridDim.x - BB) * blockDim.x;
    for (int i = tid; i < 512 * 128; i += stride) {
        g_wi0[i]             = wi0f[i];
        g_wi0[512 * 128 + i] = wi0b[i];
    }
    for (int i = tid; i < 512 * 256; i += stride) {
        g_wi1[i]             = wi1f[i];
        g_wi1[512 * 256 + i] = wi1b[i];
    }
    for (int i = tid; i < 512; i += stride) {
        g_b0[i]       = b0f[i];
        g_b0[512 + i] = b0b[i];
        g_b1[i]       = b1f[i];
        g_b1[512 + i] = b1b[i];
    }
    const float* whs[4] = { wh0f, wh0b, wh1f, wh1b };
    for (int dl = 0; dl < 4; ++dl) {
        const float* w = whs[dl];
        for (int i = tid; i < 512 * 128; i += stride) {
            int r = i >> 7, k = i & 127;
            g_whT[dl * 65536 + k * 512 + r] = w[i];   // whT[k][r] = wh[r][k]
        }
    }
}

// ---------------- tf32 tensor-core GEMM: C[m][n] = sum_k A[m][k]*B[n][k] + bias[n] ----------------
__global__ void __launch_bounds__(256, 3) gemm_kernel(const float* __restrict__ Ain,
                                                      const int* __restrict__ gidx,
                                                      int Kd, int phase)
{
    extern __shared__ uint32_t gsm[];
    uint32_t* As = gsm;                // 64 x 132 (tf32 bits)
    uint32_t* Bs = gsm + 64 * 132;     // 64 x 132

    int m0 = blockIdx.y * 64;
    int n0 = blockIdx.x * 64;

    {
        int b  = m0 >> 9;
        int t0 = m0 & 511;
        if (t0 >= g_len[b]) return;   // uniform across CTA, before any barrier
    }

    const float* A    = phase ? g_H0  : Ain;
    const float* Bw   = phase ? g_wi1 : g_wi0;
    const float* bias = phase ? g_b1  : g_b0;

    int tid  = threadIdx.x;
    int w    = tid >> 5;
    int lane = tid & 31;
    int wm   = w & 3;           // 0..3 -> m sub-tile
    int wn   = w >> 2;          // 0..1 -> n sub-tile
    int g    = lane >> 2;       // 0..7
    int t    = lane & 3;        // 0..3

    int lr  = tid >> 2;         // 0..63 load row
    int seg = (tid & 3) * 32;   // 0,32,64,96 load col segment

    size_t arow_idx = (size_t)(gidx ? gidx[m0 + lr] : (m0 + lr)) * Kd;
    size_t brow_idx = (size_t)(n0 + lr) * Kd;

    float acc[4][4] = {};

    int nch = Kd >> 7;          // K chunks of 128
    for (int ch = 0; ch < nch; ++ch) {
        const float* arow = A  + arow_idx + ch * 128 + seg;
        const float* brow = Bw + brow_idx + ch * 128 + seg;
        __syncthreads();
#pragma unroll
        for (int i = 0; i < 8; ++i) {
            float4 av = *(const float4*)(arow + 4 * i);
            float4 bv = *(const float4*)(brow + 4 * i);
            uint4 au = make_uint4(tf32cvt(av.x), tf32cvt(av.y), tf32cvt(av.z), tf32cvt(av.w));
            uint4 bu = make_uint4(tf32cvt(bv.x), tf32cvt(bv.y), tf32cvt(bv.z), tf32cvt(bv.w));
            *(uint4*)&As[lr * 132 + seg + 4 * i] = au;
            *(uint4*)&Bs[lr * 132 + seg + 4 * i] = bu;
        }
        __syncthreads();

        const uint32_t* Ar0 = &As[(wm * 16 + g)     * 132];
        const uint32_t* Ar1 = &As[(wm * 16 + g + 8) * 132];
#pragma unroll
        for (int ks = 0; ks < 16; ++ks) {
            int k0 = ks * 8 + t;
            uint32_t a0 = Ar0[k0];
            uint32_t a1 = Ar1[k0];
            uint32_t a2 = Ar0[k0 + 4];
            uint32_t a3 = Ar1[k0 + 4];
#pragma unroll
            for (int nt = 0; nt < 4; ++nt) {
                const uint32_t* Br = &Bs[(wn * 32 + nt * 8 + g) * 132];
                uint32_t b0 = Br[k0];
                uint32_t b1 = Br[k0 + 4];
                mma_tf32(acc[nt], a0, a1, a2, a3, b0, b1);
            }
        }
    }

    int mr0 = m0 + wm * 16 + g;
    int mr1 = mr0 + 8;
#pragma unroll
    for (int nt = 0; nt < 4; ++nt) {
        int nc = n0 + wn * 32 + nt * 8 + 2 * t;
        float2 bo = *(const float2*)&bias[nc];
        *(float2*)&g_G[(size_t)mr0 * 1024 + nc] = make_float2(acc[nt][0] + bo.x, acc[nt][1] + bo.y);
        *(float2*)&g_G[(size_t)mr1 * 1024 + nc] = make_float2(acc[nt][2] + bo.x, acc[nt][3] + bo.y);
    }
}

// ---------------- LSTM recurrence (R9, measured best) ----------------
__device__ __forceinline__ float tanh_mufu(float x) {
    float r;
    asm("tanh.approx.f32 %0, %1;" : "=f"(r) : "f"(x));
    return r;
}
__device__ __forceinline__ float sigm(float x) {
    return fmaf(0.5f, tanh_mufu(0.5f * x), 0.5f);
}

__global__ void __launch_bounds__(256, 1) lstm_kernel(int layer)
{
    int b   = blockIdx.x;
    int dir = blockIdx.y;
    const float* whT = g_whT + (size_t)(layer * 2 + dir) * 65536;  // [k][512]

    extern __shared__ float sm[];
    uint32_t* pwsb = (uint32_t*)sm;                    // KS*256 u32: packed bf16 row-pairs
    float* zbuf  = sm + (KS * 512 * 2) / 4;            // 512
    float* hpair = zbuf + 512;                         // 128 float2 (h duplicated)

    int tid = threadIdx.x;

    for (int c = 0; c < KS / 4; ++c) {
        uint32_t v[4];
#pragma unroll
        for (int j = 0; j < 4; ++j) {
            float2 w = *(const float2*)&whT[(4 * c + j) * 512 + 2 * tid];
            __nv_bfloat162 bb = __float22bfloat162_rn(w);
            v[j] = *(uint32_t*)&bb;
        }
        *(uint4*)&pwsb[(c * 256 + tid) * 4] = make_uint4(v[0], v[1], v[2], v[3]);
    }

    ull tw[TAILK];
#pragma unroll
    for (int j = 0; j < TAILK; ++j)
        tw[j] = *(const ull*)&whT[(KS + j) * 512 + 2 * tid];

    if (tid < 128) *(float2*)&hpair[2 * tid] = make_float2(0.f, 0.f);
    float c_st = 0.f;
    int len = g_len[b];
    float* Hout = layer ? g_H1 : g_H0;
    __syncthreads();

    const ulonglong2* hp = (const ulonglong2*)hpair;

    int t = (dir == 0) ? 0 : (len - 1);
    ull gc = *(const ull*)&g_G[((size_t)(b * TT + t)) * 1024 + dir * 512 + 2 * tid];

    for (int s = 0; s < len; ++s) {
        int sn = s + 1;
        int tnx;
        if (dir == 0) tnx = sn;
        else          tnx = len - 1 - sn;
        if (sn >= len) tnx = t;   // dummy (value unused on last iter)
        ull gn = *(const ull*)&g_G[((size_t)(b * TT + tnx)) * 1024 + dir * 512 + 2 * tid];

        ull acc0 = gc, acc1 = 0, acc2 = 0, acc3 = 0;
#pragma unroll
        for (int c = 0; c < KS / 4; ++c) {
            uint4 w4 = *(const uint4*)&pwsb[(c * 256 + tid) * 4];
            ulonglong2 hv0 = hp[2 * c];
            ulonglong2 hv1 = hp[2 * c + 1];
            acc0 = fma2(bf2up(w4.x), hv0.x, acc0);
            acc1 = fma2(bf2up(w4.y), hv0.y, acc1);
            acc2 = fma2(bf2up(w4.z), hv1.x, acc2);
            acc3 = fma2(bf2up(w4.w), hv1.y, acc3);
        }
#pragma unroll
        for (int j = 0; j < TAILK; j += 2) {
            ulonglong2 hv = hp[(KS + j) >> 1];
            acc0 = fma2(tw[j],     hv.x, acc0);
            acc1 = fma2(tw[j + 1], hv.y, acc1);
        }
        float2 z = unpack2(add2(add2(acc0, acc1), add2(acc2, acc3)));
        *(float2*)&zbuf[2 * tid] = z;
        __syncthreads();

        if (tid < 128) {
            float zi = zbuf[tid],       zf = zbuf[128 + tid];
            float zg = zbuf[256 + tid], zo = zbuf[384 + tid];
            c_st = sigm(zf) * c_st + sigm(zi) * tanh_mufu(zg);
            float h = sigm(zo) * tanh_mufu(c_st);
            *(float2*)&hpair[2 * tid] = make_float2(h, h);
            Hout[((size_t)(b * TT + t)) * 256 + dir * 128 + tid] = h;
        }
        __syncthreads();
        gc = gn;
        t  = tnx;
    }
}

// ---------------- emissions: e = H1 @ w_out^T + b_out (length-clipped) ----------------
__global__ void emis_kernel(const float* __restrict__ w_out, const float* __restrict__ b_out)
{
    __shared__ float ws[32 * 257];
    __shared__ float hs[8][256];
    __shared__ float bs[32];

    int m0 = blockIdx.x * 8;
    {
        int b  = m0 >> 9;
        int t0 = m0 & 511;
        if (t0 >= g_len[b]) return;   // whole block padded; output never read
    }

    int tid = threadIdx.x;
    for (int i = tid; i < 32 * 256; i += 256)
        ws[(i >> 8) * 257 + (i & 255)] = w_out[i];
    if (tid < 32) bs[tid] = b_out[tid];

    int w    = tid >> 5;
    int lane = tid & 31;
    int m    = m0 + w;
    for (int d = lane; d < 256; d += 32)
        hs[w][d] = g_H1[(size_t)m * 256 + d];
    __syncthreads();

    float e = bs[lane];
#pragma unroll 8
    for (int d = 0; d < 256; ++d)
        e += hs[w][d] * ws[lane * 257 + d];
    g_E[(size_t)m * 32 + lane] = e;
}

// ---------------- CRF: warp per batch, exp-space inner loop ----------------
__global__ void crf_kernel(const int* __restrict__ y, const float* __restrict__ trans,
                           float* __restrict__ out)
{
    int b    = blockIdx.x;
    int lane = threadIdx.x;
    __shared__ float tr[32 * 33];
    for (int i = lane; i < 1024; i += 32)
        tr[(i >> 5) * 33 + (i & 31)] = trans[i];
    __syncwarp();

    // preload exp(trans[lane][k]) into registers (exp(-10000) -> 0 exactly)
    float etr[32];
#pragma unroll
    for (int k = 0; k < 32; ++k)
        etr[k] = __expf(tr[lane * 33 + k]);

    int len = g_len[b];
    const float* Eb = g_E + (size_t)b * TT * 32;

    float score = (lane == SOS) ? 0.f : -10000.f;
    for (int t = 0; t < len; ++t) {
        float e = Eb[t * 32 + lane];
        float m = score;
#pragma unroll
        for (int off = 16; off; off >>= 1)
            m = fmaxf(m, __shfl_xor_sync(0xffffffffu, m, off));
        float es = __expf(score - m);
        // 4 interleaved accumulators to break the serial fma chain
        float s0 = 0.f, s1 = 0.f, s2 = 0.f, s3 = 0.f;
#pragma unroll
        for (int k = 0; k < 32; k += 4) {
            s0 = fmaf(etr[k],     __shfl_sync(0xffffffffu, es, k),     s0);
            s1 = fmaf(etr[k + 1], __shfl_sync(0xffffffffu, es, k + 1), s1);
            s2 = fmaf(etr[k + 2], __shfl_sync(0xffffffffu, es, k + 2), s2);
            s3 = fmaf(etr[k + 3], __shfl_sync(0xffffffffu, es, k + 3), s3);
        }
        score = e + m + __logf((s0 + s1) + (s2 + s3));
    }

    float v2 = score + tr[EOS * 33 + lane];
    float m = v2;
#pragma unroll
    for (int off = 16; off; off >>= 1) m = fmaxf(m, __shfl_xor_sync(0xffffffffu, m, off));
    float s = expf(v2 - m);
#pragma unroll
    for (int off = 16; off; off >>= 1) s += __shfl_xor_sync(0xffffffffu, s, off);
    float logZ = m + logf(s);

    const int* yb = y + b * (TT + 1);
    float g = 0.f;
    for (int t = lane; t < len; t += 32) {
        int y1 = yb[t + 1];
        int y0 = yb[t];
        g += Eb[t * 32 + y1] + tr[y1 * 33 + y0];
    }
#pragma unroll
    for (int off = 16; off; off >>= 1) g += __shfl_xor_sync(0xffffffffu, g, off);

    if (lane == 0) {
        g += tr[EOS * 33 + yb[len]];
        out[b] = logZ - g;
    }
}

// ---------------- launch ----------------
extern "C" void kernel_launch(void* const* d_in, const int* in_sizes, int n_in,
                              void* d_out, int out_size)
{
    const int*   x      = (const int*)  d_in[0];
    const int*   y      = (const int*)  d_in[1];
    const float* embed  = (const float*)d_in[2];
    const float* wi_l0f = (const float*)d_in[3];
    const float* wh_l0f = (const float*)d_in[4];
    const float* b_l0f  = (const float*)d_in[5];
    const float* wi_l0b = (const float*)d_in[6];
    const float* wh_l0b = (const float*)d_in[7];
    const float* b_l0b  = (const float*)d_in[8];
    const float* wi_l1f = (const float*)d_in[9];
    const float* wh_l1f = (const float*)d_in[10];
    const float* b_l1f  = (const float*)d_in[11];
    const float* wi_l1b = (const float*)d_in[12];
    const float* wh_l1b = (const float*)d_in[13];
    const float* b_l1b  = (const float*)d_in[14];
    const float* w_out  = (const float*)d_in[15];
    const float* b_out  = (const float*)d_in[16];
    const float* trans  = (const float*)d_in[17];
    float* out = (float*)d_out;

    cudaFuncSetAttribute(lstm_kernel, cudaFuncAttributeMaxDynamicSharedMemorySize, LSTM_SMEM);
    cudaFuncSetAttribute(gemm_kernel, cudaFuncAttributeMaxDynamicSharedMemorySize, GEMM_SMEM);

    prep_kernel<<<BB + 256, 256>>>(x,
                                   wi_l0f, wi_l0b, b_l0f, b_l0b,
                                   wi_l1f, wi_l1b, b_l1f, b_l1b,
                                   wh_l0f, wh_l0b, wh_l1f, wh_l1b);       // launch 1

    gemm_kernel<<<dim3(16, 512), 256, GEMM_SMEM>>>(embed, x, 128, 0);     // launch 2
    lstm_kernel<<<dim3(BB, 2), 256, LSTM_SMEM>>>(0);                      // launch 3

    gemm_kernel<<<dim3(16, 512), 256, GEMM_SMEM>>>(nullptr, nullptr, 256, 1); // launch 4
    lstm_kernel<<<dim3(BB, 2), 256, LSTM_SMEM>>>(1);                      // launch 5

    emis_kernel<<<(BB * TT) / 8, 256>>>(w_out, b_out);                    // launch 6 (profiled)
    crf_kernel<<<BB, 32>>>(y, trans, out);                                // launch 7
}

// round 14
// speedup vs baseline: 1.0679x; 1.0679x over previous
#include <cuda_runtime.h>
#include <cuda_bf16.h>
#include <math.h>
#include <stdint.h>

// Problem constants
#define BB   64
#define TT   512
#define EE   128
#define HH   256
#define HP   128
#define KK   32
#define SOS  2
#define EOS  3

// LSTM recurrence split: KS h-slices of wh in smem (bf16), TAILK in registers (fp32)
#define KS    48
#define TAILK 80
#define LSTM_SMEM (KS*512*2 + (512 + 256) * 4)

// GEMM tile smem: two 64x128 tiles padded to 132 words/row
#define GEMM_SMEM (2 * 64 * 132 * 4)

typedef unsigned long long ull;

__device__ __forceinline__ ull fma2(ull a, ull b, ull c) {
    ull d;
    asm("fma.rn.f32x2 %0, %1, %2, %3;" : "=l"(d) : "l"(a), "l"(b), "l"(c));
    return d;
}
__device__ __forceinline__ ull add2(ull a, ull b) {
    ull d;
    asm("add.rn.f32x2 %0, %1, %2;" : "=l"(d) : "l"(a), "l"(b));
    return d;
}
__device__ __forceinline__ float2 unpack2(ull a) {
    float2 r;
    asm("mov.b64 {%0, %1}, %2;" : "=f"(r.x), "=f"(r.y) : "l"(a));
    return r;
}
// packed (bf16 lo, bf16 hi) -> f32x2 pair (exact: bf16 is top 16 bits of f32)
__device__ __forceinline__ ull bf2up(uint32_t r) {
    ull d;
    asm("{ .reg .b32 lo, hi;\n\t"
        "  shl.b32 lo, %1, 16;\n\t"
        "  and.b32 hi, %1, 0xFFFF0000;\n\t"
        "  mov.b64 %0, {lo, hi}; }"
        : "=l"(d) : "r"(r));
    return d;
}
__device__ __forceinline__ uint32_t tf32cvt(float x) {
    uint32_t u;
    asm("cvt.rna.tf32.f32 %0, %1;" : "=r"(u) : "f"(x));
    return u;
}
__device__ __forceinline__ void mma_tf32(float c[4],
                                         uint32_t a0, uint32_t a1, uint32_t a2, uint32_t a3,
                                         uint32_t b0, uint32_t b1) {
    asm("mma.sync.aligned.m16n8k8.row.col.f32.tf32.tf32.f32 "
        "{%0,%1,%2,%3},{%4,%5,%6,%7},{%8,%9},{%0,%1,%2,%3};"
        : "+f"(c[0]), "+f"(c[1]), "+f"(c[2]), "+f"(c[3])
        : "r"(a0), "r"(a1), "r"(a2), "r"(a3), "r"(b0), "r"(b1));
}

// ---------------- device scratch ----------------
__device__ float g_G [ (size_t)BB * TT * 1024 ];   // gate preactivations, both dirs
__device__ float g_H0[ (size_t)BB * TT * 256 ];
__device__ float g_H1[ (size_t)BB * TT * 256 ];
__device__ float g_E [ (size_t)BB * TT * 32 ];
__device__ float g_whT[ 4 * 128 * 512 ];           // [dl][k][512]
__device__ float g_wi0[ 1024 * 128 ];
__device__ float g_wi1[ 1024 * 256 ];
__device__ float g_b0 [ 1024 ];
__device__ float g_b1 [ 1024 ];
__device__ int   g_len[ BB ];

// ---------------- prep: lengths + all weight packing in one launch ----------------
__global__ void prep_kernel(const int* __restrict__ x,
                            const float* __restrict__ wi0f, const float* __restrict__ wi0b,
                            const float* __restrict__ b0f,  const float* __restrict__ b0b,
                            const float* __restrict__ wi1f, const float* __restrict__ wi1b,
                            const float* __restrict__ b1f,  const float* __restrict__ b1b,
                            const float* __restrict__ wh0f, const float* __restrict__ wh0b,
                            const float* __restrict__ wh1f, const float* __restrict__ wh1b)
{
    if (blockIdx.x < BB) {
        int b = blockIdx.x;
        __shared__ int cnt;
        if (threadIdx.x == 0) cnt = 0;
        __syncthreads();
        int local = 0;
        for (int t = threadIdx.x; t < TT; t += blockDim.x)
            local += (x[b * TT + t] > 0) ? 1 : 0;
        atomicAdd(&cnt, local);
        __syncthreads();
        if (threadIdx.x == 0) g_len[b] = cnt;
        return;
    }

    int tid = (blockIdx.x - BB) * blockDim.x + threadIdx.x;
    int stride = (gridDim.x - BB) * blockDim.x;
    for (int i = tid; i < 512 * 128; i += stride) {
        g_wi0[i]             = wi0f[i];
        g_wi0[512 * 128 + i] = wi0b[i];
    }
    for (int i = tid; i < 512 * 256; i += stride) {
        g_wi1[i]             = wi1f[i];
        g_wi1[512 * 256 + i] = wi1b[i];
    }
    for (int i = tid; i < 512; i += stride) {
        g_b0[i]       = b0f[i];
        g_b0[512 + i] = b0b[i];
        g_b1[i]       = b1f[i];
        g_b1[512 + i] = b1b[i];
    }
    const float* whs[4] = { wh0f, wh0b, wh1f, wh1b };
    for (int dl = 0; dl < 4; ++dl) {
        const float* w = whs[dl];
        for (int i = tid; i < 512 * 128; i += stride) {
            int r = i >> 7, k = i & 127;
            g_whT[dl * 65536 + k * 512 + r] = w[i];   // whT[k][r] = wh[r][k]
        }
    }
}

// ---------------- tf32 tensor-core GEMM (R12 config: no occupancy cap) ----------------
__global__ void __launch_bounds__(256, 1) gemm_kernel(const float* __restrict__ Ain,
                                                      const int* __restrict__ gidx,
                                                      int Kd, int phase)
{
    extern __shared__ uint32_t gsm[];
    uint32_t* As = gsm;                // 64 x 132 (tf32 bits)
    uint32_t* Bs = gsm + 64 * 132;     // 64 x 132

    int m0 = blockIdx.y * 64;
    int n0 = blockIdx.x * 64;

    {
        int b  = m0 >> 9;
        int t0 = m0 & 511;
        if (t0 >= g_len[b]) return;   // uniform across CTA, before any barrier
    }

    const float* A    = phase ? g_H0  : Ain;
    const float* Bw   = phase ? g_wi1 : g_wi0;
    const float* bias = phase ? g_b1  : g_b0;

    int tid  = threadIdx.x;
    int w    = tid >> 5;
    int lane = tid & 31;
    int wm   = w & 3;           // 0..3 -> m sub-tile
    int wn   = w >> 2;          // 0..1 -> n sub-tile
    int g    = lane >> 2;       // 0..7
    int t    = lane & 3;        // 0..3

    int lr  = tid >> 2;         // 0..63 load row
    int seg = (tid & 3) * 32;   // 0,32,64,96 load col segment

    size_t arow_idx = (size_t)(gidx ? gidx[m0 + lr] : (m0 + lr)) * Kd;
    size_t brow_idx = (size_t)(n0 + lr) * Kd;

    float acc[4][4] = {};

    int nch = Kd >> 7;          // K chunks of 128
    for (int ch = 0; ch < nch; ++ch) {
        const float* arow = A  + arow_idx + ch * 128 + seg;
        const float* brow = Bw + brow_idx + ch * 128 + seg;
        __syncthreads();
#pragma unroll
        for (int i = 0; i < 8; ++i) {
            float4 av = *(const float4*)(arow + 4 * i);
            float4 bv = *(const float4*)(brow + 4 * i);
            uint4 au = make_uint4(tf32cvt(av.x), tf32cvt(av.y), tf32cvt(av.z), tf32cvt(av.w));
            uint4 bu = make_uint4(tf32cvt(bv.x), tf32cvt(bv.y), tf32cvt(bv.z), tf32cvt(bv.w));
            *(uint4*)&As[lr * 132 + seg + 4 * i] = au;
            *(uint4*)&Bs[lr * 132 + seg + 4 * i] = bu;
        }
        __syncthreads();

        const uint32_t* Ar0 = &As[(wm * 16 + g)     * 132];
        const uint32_t* Ar1 = &As[(wm * 16 + g + 8) * 132];
#pragma unroll
        for (int ks = 0; ks < 16; ++ks) {
            int k0 = ks * 8 + t;
            uint32_t a0 = Ar0[k0];
            uint32_t a1 = Ar1[k0];
            uint32_t a2 = Ar0[k0 + 4];
            uint32_t a3 = Ar1[k0 + 4];
#pragma unroll
            for (int nt = 0; nt < 4; ++nt) {
                const uint32_t* Br = &Bs[(wn * 32 + nt * 8 + g) * 132];
                uint32_t b0 = Br[k0];
                uint32_t b1 = Br[k0 + 4];
                mma_tf32(acc[nt], a0, a1, a2, a3, b0, b1);
            }
        }
    }

    int mr0 = m0 + wm * 16 + g;
    int mr1 = mr0 + 8;
#pragma unroll
    for (int nt = 0; nt < 4; ++nt) {
        int nc = n0 + wn * 32 + nt * 8 + 2 * t;
        float2 bo = *(const float2*)&bias[nc];
        *(float2*)&g_G[(size_t)mr0 * 1024 + nc] = make_float2(acc[nt][0] + bo.x, acc[nt][1] + bo.y);
        *(float2*)&g_G[(size_t)mr1 * 1024 + nc] = make_float2(acc[nt][2] + bo.x, acc[nt][3] + bo.y);
    }
}

// ---------------- LSTM recurrence (R9, measured best) ----------------
__device__ __forceinline__ float tanh_mufu(float x) {
    float r;
    asm("tanh.approx.f32 %0, %1;" : "=f"(r) : "f"(x));
    return r;
}
__device__ __forceinline__ float sigm(float x) {
    return fmaf(0.5f, tanh_mufu(0.5f * x), 0.5f);
}

__global__ void __launch_bounds__(256, 1) lstm_kernel(int layer)
{
    int b   = blockIdx.x;
    int dir = blockIdx.y;
    const float* whT = g_whT + (size_t)(layer * 2 + dir) * 65536;  // [k][512]

    extern __shared__ float sm[];
    uint32_t* pwsb = (uint32_t*)sm;                    // KS*256 u32: packed bf16 row-pairs
    float* zbuf  = sm + (KS * 512 * 2) / 4;            // 512
    float* hpair = zbuf + 512;                         // 128 float2 (h duplicated)

    int tid = threadIdx.x;

    for (int c = 0; c < KS / 4; ++c) {
        uint32_t v[4];
#pragma unroll
        for (int j = 0; j < 4; ++j) {
            float2 w = *(const float2*)&whT[(4 * c + j) * 512 + 2 * tid];
            __nv_bfloat162 bb = __float22bfloat162_rn(w);
            v[j] = *(uint32_t*)&bb;
        }
        *(uint4*)&pwsb[(c * 256 + tid) * 4] = make_uint4(v[0], v[1], v[2], v[3]);
    }

    ull tw[TAILK];
#pragma unroll
    for (int j = 0; j < TAILK; ++j)
        tw[j] = *(const ull*)&whT[(KS + j) * 512 + 2 * tid];

    if (tid < 128) *(float2*)&hpair[2 * tid] = make_float2(0.f, 0.f);
    float c_st = 0.f;
    int len = g_len[b];
    float* Hout = layer ? g_H1 : g_H0;
    __syncthreads();

    const ulonglong2* hp = (const ulonglong2*)hpair;

    int t = (dir == 0) ? 0 : (len - 1);
    ull gc = *(const ull*)&g_G[((size_t)(b * TT + t)) * 1024 + dir * 512 + 2 * tid];

    for (int s = 0; s < len; ++s) {
        int sn = s + 1;
        int tnx;
        if (dir == 0) tnx = sn;
        else          tnx = len - 1 - sn;
        if (sn >= len) tnx = t;   // dummy (value unused on last iter)
        ull gn = *(const ull*)&g_G[((size_t)(b * TT + tnx)) * 1024 + dir * 512 + 2 * tid];

        ull acc0 = gc, acc1 = 0, acc2 = 0, acc3 = 0;
#pragma unroll
        for (int c = 0; c < KS / 4; ++c) {
            uint4 w4 = *(const uint4*)&pwsb[(c * 256 + tid) * 4];
            ulonglong2 hv0 = hp[2 * c];
            ulonglong2 hv1 = hp[2 * c + 1];
            acc0 = fma2(bf2up(w4.x), hv0.x, acc0);
            acc1 = fma2(bf2up(w4.y), hv0.y, acc1);
            acc2 = fma2(bf2up(w4.z), hv1.x, acc2);
            acc3 = fma2(bf2up(w4.w), hv1.y, acc3);
        }
#pragma unroll
        for (int j = 0; j < TAILK; j += 2) {
            ulonglong2 hv = hp[(KS + j) >> 1];
            acc0 = fma2(tw[j],     hv.x, acc0);
            acc1 = fma2(tw[j + 1], hv.y, acc1);
        }
        float2 z = unpack2(add2(add2(acc0, acc1), add2(acc2, acc3)));
        *(float2*)&zbuf[2 * tid] = z;
        __syncthreads();

        if (tid < 128) {
            float zi = zbuf[tid],       zf = zbuf[128 + tid];
            float zg = zbuf[256 + tid], zo = zbuf[384 + tid];
            c_st = sigm(zf) * c_st + sigm(zi) * tanh_mufu(zg);
            float h = sigm(zo) * tanh_mufu(c_st);
            *(float2*)&hpair[2 * tid] = make_float2(h, h);
            Hout[((size_t)(b * TT + t)) * 256 + dir * 128 + tid] = h;
        }
        __syncthreads();
        gc = gn;
        t  = tnx;
    }
}

// ---------------- emissions: e = H1 @ w_out^T + b_out (length-clipped) ----------------
__global__ void emis_kernel(const float* __restrict__ w_out, const float* __restrict__ b_out)
{
    __shared__ float ws[32 * 257];
    __shared__ float hs[8][256];
    __shared__ float bs[32];

    int m0 = blockIdx.x * 8;
    {
        int b  = m0 >> 9;
        int t0 = m0 & 511;
        if (t0 >= g_len[b]) return;   // whole block padded; output never read
    }

    int tid = threadIdx.x;
    for (int i = tid; i < 32 * 256; i += 256)
        ws[(i >> 8) * 257 + (i & 255)] = w_out[i];
    if (tid < 32) bs[tid] = b_out[tid];

    int w    = tid >> 5;
    int lane = tid & 31;
    int m    = m0 + w;
    for (int d = lane; d < 256; d += 32)
        hs[w][d] = g_H1[(size_t)m * 256 + d];
    __syncthreads();

    float e = bs[lane];
#pragma unroll 8
    for (int d = 0; d < 256; ++d)
        e += hs[w][d] * ws[lane * 257 + d];
    g_E[(size_t)m * 32 + lane] = e;
}

// ---------------- CRF: warp per batch, exp-space inner loop ----------------
__global__ void crf_kernel(const int* __restrict__ y, const float* __restrict__ trans,
                           float* __restrict__ out)
{
    int b    = blockIdx.x;
    int lane = threadIdx.x;
    __shared__ float tr[32 * 33];
    for (int i = lane; i < 1024; i += 32)
        tr[(i >> 5) * 33 + (i & 31)] = trans[i];
    __syncwarp();

    // preload exp(trans[lane][k]) into registers (exp(-10000) -> 0 exactly)
    float etr[32];
#pragma unroll
    for (int k = 0; k < 32; ++k)
        etr[k] = __expf(tr[lane * 33 + k]);

    int len = g_len[b];
    const float* Eb = g_E + (size_t)b * TT * 32;

    float score = (lane == SOS) ? 0.f : -10000.f;
    for (int t = 0; t < len; ++t) {
        float e = Eb[t * 32 + lane];
        float m = score;
#pragma unroll
        for (int off = 16; off; off >>= 1)
            m = fmaxf(m, __shfl_xor_sync(0xffffffffu, m, off));
        float es = __expf(score - m);
        float s0 = 0.f, s1 = 0.f, s2 = 0.f, s3 = 0.f;
#pragma unroll
        for (int k = 0; k < 32; k += 4) {
            s0 = fmaf(etr[k],     __shfl_sync(0xffffffffu, es, k),     s0);
            s1 = fmaf(etr[k + 1], __shfl_sync(0xffffffffu, es, k + 1), s1);
            s2 = fmaf(etr[k + 2], __shfl_sync(0xffffffffu, es, k + 2), s2);
            s3 = fmaf(etr[k + 3], __shfl_sync(0xffffffffu, es, k + 3), s3);
        }
        score = e + m + __logf((s0 + s1) + (s2 + s3));
    }

    float v2 = score + tr[EOS * 33 + lane];
    float m = v2;
#pragma unroll
    for (int off = 16; off; off >>= 1) m = fmaxf(m, __shfl_xor_sync(0xffffffffu, m, off));
    float s = expf(v2 - m);
#pragma unroll
    for (int off = 16; off; off >>= 1) s += __shfl_xor_sync(0xffffffffu, s, off);
    float logZ = m + logf(s);

    const int* yb = y + b * (TT + 1);
    float g = 0.f;
    for (int t = lane; t < len; t += 32) {
        int y1 = yb[t + 1];
        int y0 = yb[t];
        g += Eb[t * 32 + y1] + tr[y1 * 33 + y0];
    }
#pragma unroll
    for (int off = 16; off; off >>= 1) g += __shfl_xor_sync(0xffffffffu, g, off);

    if (lane == 0) {
        g += tr[EOS * 33 + yb[len]];
        out[b] = logZ - g;
    }
}

// ---------------- launch ----------------
extern "C" void kernel_launch(void* const* d_in, const int* in_sizes, int n_in,
                              void* d_out, int out_size)
{
    const int*   x      = (const int*)  d_in[0];
    const int*   y      = (const int*)  d_in[1];
    const float* embed  = (const float*)d_in[2];
    const float* wi_l0f = (const float*)d_in[3];
    const float* wh_l0f = (const float*)d_in[4];
    const float* b_l0f  = (const float*)d_in[5];
    const float* wi_l0b = (const float*)d_in[6];
    const float* wh_l0b = (const float*)d_in[7];
    const float* b_l0b  = (const float*)d_in[8];
    const float* wi_l1f = (const float*)d_in[9];
    const float* wh_l1f = (const float*)d_in[10];
    const float* b_l1f  = (const float*)d_in[11];
    const float* wi_l1b = (const float*)d_in[12];
    const float* wh_l1b = (const float*)d_in[13];
    const float* b_l1b  = (const float*)d_in[14];
    const float* w_out  = (const float*)d_in[15];
    const float* b_out  = (const float*)d_in[16];
    const float* trans  = (const float*)d_in[17];
    float* out = (float*)d_out;

    cudaFuncSetAttribute(lstm_kernel, cudaFuncAttributeMaxDynamicSharedMemorySize, LSTM_SMEM);
    cudaFuncSetAttribute(gemm_kernel, cudaFuncAttributeMaxDynamicSharedMemorySize, GEMM_SMEM);

    prep_kernel<<<BB + 256, 256>>>(x,
                                   wi_l0f, wi_l0b, b_l0f, b_l0b,
                                   wi_l1f, wi_l1b, b_l1f, b_l1b,
                                   wh_l0f, wh_l0b, wh_l1f, wh_l1b);       // launch 1

    gemm_kernel<<<dim3(16, 512), 256, GEMM_SMEM>>>(embed, x, 128, 0);     // launch 2
    lstm_kernel<<<dim3(BB, 2), 256, LSTM_SMEM>>>(0);                      // launch 3

    gemm_kernel<<<dim3(16, 512), 256, GEMM_SMEM>>>(nullptr, nullptr, 256, 1); // launch 4
    lstm_kernel<<<dim3(BB, 2), 256, LSTM_SMEM>>>(1);                      // launch 5

    emis_kernel<<<(BB * TT) / 8, 256>>>(w_out, b_out);                    // launch 6 (profiled)
    crf_kernel<<<BB, 32>>>(y, trans, out);                                // launch 7
}

// round 16
// speedup vs baseline: 1.1543x; 1.0809x over previous
#include <cuda_runtime.h>
#include <cuda_bf16.h>
#include <math.h>
#include <stdint.h>

// Problem constants
#define BB   64
#define TT   512
#define EE   128
#define HH   256
#define HP   128
#define KK   32
#define SOS  2
#define EOS  3

// LSTM recurrence split: KS h-slices of wh in smem (bf16), TAILK in registers (fp32)
#define KS    48
#define TAILK 80
#define LSTM_SMEM (KS*512*2 + (512 + 256) * 4)

// GEMM tile smem: two 64-row tiles of 64 packed-bf16 words (+4 pad) each
#define GEMM_SMEM (2 * 64 * 68 * 4)

typedef unsigned long long ull;

__device__ __forceinline__ ull fma2(ull a, ull b, ull c) {
    ull d;
    asm("fma.rn.f32x2 %0, %1, %2, %3;" : "=l"(d) : "l"(a), "l"(b), "l"(c));
    return d;
}
__device__ __forceinline__ ull add2(ull a, ull b) {
    ull d;
    asm("add.rn.f32x2 %0, %1, %2;" : "=l"(d) : "l"(a), "l"(b));
    return d;
}
__device__ __forceinline__ float2 unpack2(ull a) {
    float2 r;
    asm("mov.b64 {%0, %1}, %2;" : "=f"(r.x), "=f"(r.y) : "l"(a));
    return r;
}
// packed (bf16 lo, bf16 hi) -> f32x2 pair (exact: bf16 is top 16 bits of f32)
__device__ __forceinline__ ull bf2up(uint32_t r) {
    ull d;
    asm("{ .reg .b32 lo, hi;\n\t"
        "  shl.b32 lo, %1, 16;\n\t"
        "  and.b32 hi, %1, 0xFFFF0000;\n\t"
        "  mov.b64 %0, {lo, hi}; }"
        : "=l"(d) : "r"(r));
    return d;
}
__device__ __forceinline__ uint32_t packbf2(float2 v) {
    __nv_bfloat162 bb = __float22bfloat162_rn(v);
    return *(uint32_t*)&bb;
}
__device__ __forceinline__ void mma_bf16(float c[4],
                                         uint32_t a0, uint32_t a1, uint32_t a2, uint32_t a3,
                                         uint32_t b0, uint32_t b1) {
    asm("mma.sync.aligned.m16n8k16.row.col.f32.bf16.bf16.f32 "
        "{%0,%1,%2,%3},{%4,%5,%6,%7},{%8,%9},{%0,%1,%2,%3};"
        : "+f"(c[0]), "+f"(c[1]), "+f"(c[2]), "+f"(c[3])
        : "r"(a0), "r"(a1), "r"(a2), "r"(a3), "r"(b0), "r"(b1));
}

// ---------------- device scratch ----------------
__device__ float g_G [ (size_t)BB * TT * 1024 ];   // gate preactivations, both dirs
__device__ float g_H0[ (size_t)BB * TT * 256 ];
__device__ float g_H1[ (size_t)BB * TT * 256 ];
__device__ float g_E [ (size_t)BB * TT * 32 ];
__device__ float g_whT[ 4 * 128 * 512 ];           // [dl][k][512]
__device__ float g_wi0[ 1024 * 128 ];
__device__ float g_wi1[ 1024 * 256 ];
__device__ float g_b0 [ 1024 ];
__device__ float g_b1 [ 1024 ];
__device__ int   g_len[ BB ];

// ---------------- prep: lengths + all weight packing in one launch ----------------
__global__ void prep_kernel(const int* __restrict__ x,
                            const float* __restrict__ wi0f, const float* __restrict__ wi0b,
                            const float* __restrict__ b0f,  const float* __restrict__ b0b,
                            const float* __restrict__ wi1f, const float* __restrict__ wi1b,
                            const float* __restrict__ b1f,  const float* __restrict__ b1b,
                            const float* __restrict__ wh0f, const float* __restrict__ wh0b,
                            const float* __restrict__ wh1f, const float* __restrict__ wh1b)
{
    if (blockIdx.x < BB) {
        int b = blockIdx.x;
        __shared__ int cnt;
        if (threadIdx.x == 0) cnt = 0;
        __syncthreads();
        int local = 0;
        for (int t = threadIdx.x; t < TT; t += blockDim.x)
            local += (x[b * TT + t] > 0) ? 1 : 0;
        atomicAdd(&cnt, local);
        __syncthreads();
        if (threadIdx.x == 0) g_len[b] = cnt;
        return;
    }

    int tid = (blockIdx.x - BB) * blockDim.x + threadIdx.x;
    int stride = (gridDim.x - BB) * blockDim.x;
    for (int i = tid; i < 512 * 128; i += stride) {
        g_wi0[i]             = wi0f[i];
        g_wi0[512 * 128 + i] = wi0b[i];
    }
    for (int i = tid; i < 512 * 256; i += stride) {
        g_wi1[i]             = wi1f[i];
        g_wi1[512 * 256 + i] = wi1b[i];
    }
    for (int i = tid; i < 512; i += stride) {
        g_b0[i]       = b0f[i];
        g_b0[512 + i] = b0b[i];
        g_b1[i]       = b1f[i];
        g_b1[512 + i] = b1b[i];
    }
    const float* whs[4] = { wh0f, wh0b, wh1f, wh1b };
    for (int dl = 0; dl < 4; ++dl) {
        const float* w = whs[dl];
        for (int i = tid; i < 512 * 128; i += stride) {
            int r = i >> 7, k = i & 127;
            g_whT[dl * 65536 + k * 512 + r] = w[i];   // whT[k][r] = wh[r][k]
        }
    }
}

// ---------------- bf16 tensor-core GEMM: C[m][n] = sum_k A[m][k]*B[n][k] + bias[n] ----------------
// 64x64 CTA tile, 8 warps (4m x 2n), mma m16n8k16 bf16, fp32 accumulate.
// Tiles stored as packed bf16 pairs: word j of a row = (k=2j, k=2j+1).
__global__ void __launch_bounds__(256, 1) gemm_kernel(const float* __restrict__ Ain,
                                                      const int* __restrict__ gidx,
                                                      int Kd, int phase)
{
    extern __shared__ uint32_t gsm[];
    uint32_t* As = gsm;                // 64 x 68 words (packed bf16 pairs)
    uint32_t* Bs = gsm + 64 * 68;      // 64 x 68

    int m0 = blockIdx.y * 64;
    int n0 = blockIdx.x * 64;

    {
        int b  = m0 >> 9;
        int t0 = m0 & 511;
        if (t0 >= g_len[b]) return;   // uniform across CTA, before any barrier
    }

    const float* A    = phase ? g_H0  : Ain;
    const float* Bw   = phase ? g_wi1 : g_wi0;
    const float* bias = phase ? g_b1  : g_b0;

    int tid  = threadIdx.x;
    int w    = tid >> 5;
    int lane = tid & 31;
    int wm   = w & 3;           // 0..3 -> m sub-tile
    int wn   = w >> 2;          // 0..1 -> n sub-tile
    int g    = lane >> 2;       // 0..7
    int t    = lane & 3;        // 0..3

    int lr  = tid >> 2;         // 0..63 load row
    int sf  = (tid & 3) * 32;   // float segment 0,32,64,96
    int sw  = (tid & 3) * 16;   // word segment 0,16,32,48

    size_t arow_idx = (size_t)(gidx ? gidx[m0 + lr] : (m0 + lr)) * Kd;
    size_t brow_idx = (size_t)(n0 + lr) * Kd;

    float acc[4][4] = {};

    int nch = Kd >> 7;          // K chunks of 128
    for (int ch = 0; ch < nch; ++ch) {
        const float* arow = A  + arow_idx + ch * 128 + sf;
        const float* brow = Bw + brow_idx + ch * 128 + sf;
        __syncthreads();
#pragma unroll
        for (int i = 0; i < 8; ++i) {
            float4 av = *(const float4*)(arow + 4 * i);
            float4 bv = *(const float4*)(brow + 4 * i);
            uint2 au = make_uint2(packbf2(make_float2(av.x, av.y)),
                                  packbf2(make_float2(av.z, av.w)));
            uint2 bu = make_uint2(packbf2(make_float2(bv.x, bv.y)),
                                  packbf2(make_float2(bv.z, bv.w)));
            *(uint2*)&As[lr * 68 + sw + 2 * i] = au;
            *(uint2*)&Bs[lr * 68 + sw + 2 * i] = bu;
        }
        __syncthreads();

        const uint32_t* Ar0 = &As[(wm * 16 + g)     * 68];
        const uint32_t* Ar1 = &As[(wm * 16 + g + 8) * 68];
#pragma unroll
        for (int ks = 0; ks < 8; ++ks) {           // 8 k16-steps per 128-k chunk
            int k0 = ks * 8 + t;
            uint32_t a0 = Ar0[k0];
            uint32_t a1 = Ar1[k0];
            uint32_t a2 = Ar0[k0 + 4];
            uint32_t a3 = Ar1[k0 + 4];
#pragma unroll
            for (int nt = 0; nt < 4; ++nt) {
                const uint32_t* Br = &Bs[(wn * 32 + nt * 8 + g) * 68];
                uint32_t b0 = Br[k0];
                uint32_t b1 = Br[k0 + 4];
                mma_bf16(acc[nt], a0, a1, a2, a3, b0, b1);
            }
        }
    }

    int mr0 = m0 + wm * 16 + g;
    int mr1 = mr0 + 8;
#pragma unroll
    for (int nt = 0; nt < 4; ++nt) {
        int nc = n0 + wn * 32 + nt * 8 + 2 * t;
        float2 bo = *(const float2*)&bias[nc];
        *(float2*)&g_G[(size_t)mr0 * 1024 + nc] = make_float2(acc[nt][0] + bo.x, acc[nt][1] + bo.y);
        *(float2*)&g_G[(size_t)mr1 * 1024 + nc] = make_float2(acc[nt][2] + bo.x, acc[nt][3] + bo.y);
    }
}

// ---------------- LSTM recurrence (R9, measured best) ----------------
__device__ __forceinline__ float tanh_mufu(float x) {
    float r;
    asm("tanh.approx.f32 %0, %1;" : "=f"(r) : "f"(x));
    return r;
}
__device__ __forceinline__ float sigm(float x) {
    return fmaf(0.5f, tanh_mufu(0.5f * x), 0.5f);
}

__global__ void __launch_bounds__(256, 1) lstm_kernel(int layer)
{
    int b   = blockIdx.x;
    int dir = blockIdx.y;
    const float* whT = g_whT + (size_t)(layer * 2 + dir) * 65536;  // [k][512]

    extern __shared__ float sm[];
    uint32_t* pwsb = (uint32_t*)sm;                    // KS*256 u32: packed bf16 row-pairs
    float* zbuf  = sm + (KS * 512 * 2) / 4;            // 512
    float* hpair = zbuf + 512;                         // 128 float2 (h duplicated)

    int tid = threadIdx.x;

    for (int c = 0; c < KS / 4; ++c) {
        uint32_t v[4];
#pragma unroll
        for (int j = 0; j < 4; ++j) {
            float2 w = *(const float2*)&whT[(4 * c + j) * 512 + 2 * tid];
            v[j] = packbf2(w);
        }
        *(uint4*)&pwsb[(c * 256 + tid) * 4] = make_uint4(v[0], v[1], v[2], v[3]);
    }

    ull tw[TAILK];
#pragma unroll
    for (int j = 0; j < TAILK; ++j)
        tw[j] = *(const ull*)&whT[(KS + j) * 512 + 2 * tid];

    if (tid < 128) *(float2*)&hpair[2 * tid] = make_float2(0.f, 0.f);
    float c_st = 0.f;
    int len = g_len[b];
    float* Hout = layer ? g_H1 : g_H0;
    __syncthreads();

    const ulonglong2* hp = (const ulonglong2*)hpair;

    int t = (dir == 0) ? 0 : (len - 1);
    ull gc = *(const ull*)&g_G[((size_t)(b * TT + t)) * 1024 + dir * 512 + 2 * tid];

    for (int s = 0; s < len; ++s) {
        int sn = s + 1;
        int tnx;
        if (dir == 0) tnx = sn;
        else          tnx = len - 1 - sn;
        if (sn >= len) tnx = t;   // dummy (value unused on last iter)
        ull gn = *(const ull*)&g_G[((size_t)(b * TT + tnx)) * 1024 + dir * 512 + 2 * tid];

        ull acc0 = gc, acc1 = 0, acc2 = 0, acc3 = 0;
#pragma unroll
        for (int c = 0; c < KS / 4; ++c) {
            uint4 w4 = *(const uint4*)&pwsb[(c * 256 + tid) * 4];
            ulonglong2 hv0 = hp[2 * c];
            ulonglong2 hv1 = hp[2 * c + 1];
            acc0 = fma2(bf2up(w4.x), hv0.x, acc0);
            acc1 = fma2(bf2up(w4.y), hv0.y, acc1);
            acc2 = fma2(bf2up(w4.z), hv1.x, acc2);
            acc3 = fma2(bf2up(w4.w), hv1.y, acc3);
        }
#pragma unroll
        for (int j = 0; j < TAILK; j += 2) {
            ulonglong2 hv = hp[(KS + j) >> 1];
            acc0 = fma2(tw[j],     hv.x, acc0);
            acc1 = fma2(tw[j + 1], hv.y, acc1);
        }
        float2 z = unpack2(add2(add2(acc0, acc1), add2(acc2, acc3)));
        *(float2*)&zbuf[2 * tid] = z;
        __syncthreads();

        if (tid < 128) {
            float zi = zbuf[tid],       zf = zbuf[128 + tid];
            float zg = zbuf[256 + tid], zo = zbuf[384 + tid];
            c_st = sigm(zf) * c_st + sigm(zi) * tanh_mufu(zg);
            float h = sigm(zo) * tanh_mufu(c_st);
            *(float2*)&hpair[2 * tid] = make_float2(h, h);
            Hout[((size_t)(b * TT + t)) * 256 + dir * 128 + tid] = h;
        }
        __syncthreads();
        gc = gn;
        t  = tnx;
    }
}

// ---------------- emissions: e = H1 @ w_out^T + b_out (length-clipped) ----------------
__global__ void emis_kernel(const float* __restrict__ w_out, const float* __restrict__ b_out)
{
    __shared__ float ws[32 * 257];
    __shared__ float hs[8][256];
    __shared__ float bs[32];

    int m0 = blockIdx.x * 8;
    {
        int b  = m0 >> 9;
        int t0 = m0 & 511;
        if (t0 >= g_len[b]) return;   // whole block padded; output never read
    }

    int tid = threadIdx.x;
    for (int i = tid; i < 32 * 256; i += 256)
        ws[(i >> 8) * 257 + (i & 255)] = w_out[i];
    if (tid < 32) bs[tid] = b_out[tid];

    int w    = tid >> 5;
    int lane = tid & 31;
    int m    = m0 + w;
    for (int d = lane; d < 256; d += 32)
        hs[w][d] = g_H1[(size_t)m * 256 + d];
    __syncthreads();

    float e = bs[lane];
#pragma unroll 8
    for (int d = 0; d < 256; ++d)
        e += hs[w][d] * ws[lane * 257 + d];
    g_E[(size_t)m * 32 + lane] = e;
}

// ---------------- CRF: warp per batch, exp-space inner loop ----------------
__global__ void crf_kernel(const int* __restrict__ y, const float* __restrict__ trans,
                           float* __restrict__ out)
{
    int b    = blockIdx.x;
    int lane = threadIdx.x;
    __shared__ float tr[32 * 33];
    for (int i = lane; i < 1024; i += 32)
        tr[(i >> 5) * 33 + (i & 31)] = trans[i];
    __syncwarp();

    // preload exp(trans[lane][k]) into registers (exp(-10000) -> 0 exactly)
    float etr[32];
#pragma unroll
    for (int k = 0; k < 32; ++k)
        etr[k] = __expf(tr[lane * 33 + k]);

    int len = g_len[b];
    const float* Eb = g_E + (size_t)b * TT * 32;

    float score = (lane == SOS) ? 0.f : -10000.f;
    for (int t = 0; t < len; ++t) {
        float e = Eb[t * 32 + lane];
        float m = score;
#pragma unroll
        for (int off = 16; off; off >>= 1)
            m = fmaxf(m, __shfl_xor_sync(0xffffffffu, m, off));
        float es = __expf(score - m);
        float s0 = 0.f, s1 = 0.f, s2 = 0.f, s3 = 0.f;
#pragma unroll
        for (int k = 0; k < 32; k += 4) {
            s0 = fmaf(etr[k],     __shfl_sync(0xffffffffu, es, k),     s0);
            s1 = fmaf(etr[k + 1], __shfl_sync(0xffffffffu, es, k + 1), s1);
            s2 = fmaf(etr[k + 2], __shfl_sync(0xffffffffu, es, k + 2), s2);
            s3 = fmaf(etr[k + 3], __shfl_sync(0xffffffffu, es, k + 3), s3);
        }
        score = e + m + __logf((s0 + s1) + (s2 + s3));
    }

    float v2 = score + tr[EOS * 33 + lane];
    float m = v2;
#pragma unroll
    for (int off = 16; off; off >>= 1) m = fmaxf(m, __shfl_xor_sync(0xffffffffu, m, off));
    float s = expf(v2 - m);
#pragma unroll
    for (int off = 16; off; off >>= 1) s += __shfl_xor_sync(0xffffffffu, s, off);
    float logZ = m + logf(s);

    const int* yb = y + b * (TT + 1);
    float g = 0.f;
    for (int t = lane; t < len; t += 32) {
        int y1 = yb[t + 1];
        int y0 = yb[t];
        g += Eb[t * 32 + y1] + tr[y1 * 33 + y0];
    }
#pragma unroll
    for (int off = 16; off; off >>= 1) g += __shfl_xor_sync(0xffffffffu, g, off);

    if (lane == 0) {
        g += tr[EOS * 33 + yb[len]];
        out[b] = logZ - g;
    }
}

// ---------------- launch ----------------
extern "C" void kernel_launch(void* const* d_in, const int* in_sizes, int n_in,
                              void* d_out, int out_size)
{
    const int*   x      = (const int*)  d_in[0];
    const int*   y      = (const int*)  d_in[1];
    const float* embed  = (const float*)d_in[2];
    const float* wi_l0f = (const float*)d_in[3];
    const float* wh_l0f = (const float*)d_in[4];
    const float* b_l0f  = (const float*)d_in[5];
    const float* wi_l0b = (const float*)d_in[6];
    const float* wh_l0b = (const float*)d_in[7];
    const float* b_l0b  = (const float*)d_in[8];
    const float* wi_l1f = (const float*)d_in[9];
    const float* wh_l1f = (const float*)d_in[10];
    const float* b_l1f  = (const float*)d_in[11];
    const float* wi_l1b = (const float*)d_in[12];
    const float* wh_l1b = (const float*)d_in[13];
    const float* b_l1b  = (const float*)d_in[14];
    const float* w_out  = (const float*)d_in[15];
    const float* b_out  = (const float*)d_in[16];
    const float* trans  = (const float*)d_in[17];
    float* out = (float*)d_out;

    cudaFuncSetAttribute(lstm_kernel, cudaFuncAttributeMaxDynamicSharedMemorySize, LSTM_SMEM);
    cudaFuncSetAttribute(gemm_kernel, cudaFuncAttributeMaxDynamicSharedMemorySize, GEMM_SMEM);

    prep_kernel<<<BB + 256, 256>>>(x,
                                   wi_l0f, wi_l0b, b_l0f, b_l0b,
                                   wi_l1f, wi_l1b, b_l1f, b_l1b,
                                   wh_l0f, wh_l0b, wh_l1f, wh_l1b);       // launch 1

    gemm_kernel<<<dim3(16, 512), 256, GEMM_SMEM>>>(embed, x, 128, 0);     // launch 2
    lstm_kernel<<<dim3(BB, 2), 256, LSTM_SMEM>>>(0);                      // launch 3

    gemm_kernel<<<dim3(16, 512), 256, GEMM_SMEM>>>(nullptr, nullptr, 256, 1); // launch 4
    lstm_kernel<<<dim3(BB, 2), 256, LSTM_SMEM>>>(1);                      // launch 5

    emis_kernel<<<(BB * TT) / 8, 256>>>(w_out, b_out);                    // launch 6
    crf_kernel<<<BB, 32>>>(y, trans, out);                                // launch 7
}

// round 17
// speedup vs baseline: 1.1598x; 1.0048x over previous
#include <cuda_runtime.h>
#include <cuda_bf16.h>
#include <math.h>
#include <stdint.h>

// Problem constants
#define BB   64
#define TT   512
#define EE   128
#define HH   256
#define HP   128
#define KK   32
#define SOS  2
#define EOS  3

// LSTM recurrence split: KS h-slices of wh in smem (bf16), TAILK in registers (fp32)
#define KS    48
#define TAILK 80
#define LSTM_SMEM (KS*512*2 + (512 + 256) * 4)

// GEMM tile smem: A 64x68 + B 128x68 packed-bf16 words
#define GEMM_SMEM ((64 + 128) * 68 * 4)

typedef unsigned long long ull;

__device__ __forceinline__ ull fma2(ull a, ull b, ull c) {
    ull d;
    asm("fma.rn.f32x2 %0, %1, %2, %3;" : "=l"(d) : "l"(a), "l"(b), "l"(c));
    return d;
}
__device__ __forceinline__ ull add2(ull a, ull b) {
    ull d;
    asm("add.rn.f32x2 %0, %1, %2;" : "=l"(d) : "l"(a), "l"(b));
    return d;
}
__device__ __forceinline__ float2 unpack2(ull a) {
    float2 r;
    asm("mov.b64 {%0, %1}, %2;" : "=f"(r.x), "=f"(r.y) : "l"(a));
    return r;
}
__device__ __forceinline__ ull bf2up(uint32_t r) {
    ull d;
    asm("{ .reg .b32 lo, hi;\n\t"
        "  shl.b32 lo, %1, 16;\n\t"
        "  and.b32 hi, %1, 0xFFFF0000;\n\t"
        "  mov.b64 %0, {lo, hi}; }"
        : "=l"(d) : "r"(r));
    return d;
}
__device__ __forceinline__ uint32_t packbf2(float2 v) {
    __nv_bfloat162 bb = __float22bfloat162_rn(v);
    return *(uint32_t*)&bb;
}
__device__ __forceinline__ void mma_bf16(float c[4],
                                         uint32_t a0, uint32_t a1, uint32_t a2, uint32_t a3,
                                         uint32_t b0, uint32_t b1) {
    asm("mma.sync.aligned.m16n8k16.row.col.f32.bf16.bf16.f32 "
        "{%0,%1,%2,%3},{%4,%5,%6,%7},{%8,%9},{%0,%1,%2,%3};"
        : "+f"(c[0]), "+f"(c[1]), "+f"(c[2]), "+f"(c[3])
        : "r"(a0), "r"(a1), "r"(a2), "r"(a3), "r"(b0), "r"(b1));
}

// ---------------- device scratch ----------------
__device__ float g_G [ (size_t)BB * TT * 1024 ];   // gate preactivations, both dirs
__device__ float g_H0[ (size_t)BB * TT * 256 ];
__device__ float g_H1[ (size_t)BB * TT * 256 ];
__device__ float g_E [ (size_t)BB * TT * 32 ];
__device__ float g_whT[ 4 * 128 * 512 ];           // [dl][k][512]
__device__ float g_wi0[ 1024 * 128 ];
__device__ float g_wi1[ 1024 * 256 ];
__device__ float g_b0 [ 1024 ];
__device__ float g_b1 [ 1024 ];
__device__ int   g_len[ BB ];

// ---------------- prep: lengths + copies + coalesced wh transpose ----------------
// blocks [0,BB): lengths; [BB, BB+256): copies; [BB+256, BB+512): wh transpose tiles
__global__ void prep_kernel(const int* __restrict__ x,
                            const float* __restrict__ wi0f, const float* __restrict__ wi0b,
                            const float* __restrict__ b0f,  const float* __restrict__ b0b,
                            const float* __restrict__ wi1f, const float* __restrict__ wi1b,
                            const float* __restrict__ b1f,  const float* __restrict__ b1b,
                            const float* __restrict__ wh0f, const float* __restrict__ wh0b,
                            const float* __restrict__ wh1f, const float* __restrict__ wh1b)
{
    if (blockIdx.x < BB) {
        int b = blockIdx.x;
        __shared__ int cnt;
        if (threadIdx.x == 0) cnt = 0;
        __syncthreads();
        int local = 0;
        for (int t = threadIdx.x; t < TT; t += blockDim.x)
            local += (x[b * TT + t] > 0) ? 1 : 0;
        atomicAdd(&cnt, local);
        __syncthreads();
        if (threadIdx.x == 0) g_len[b] = cnt;
        return;
    }

    if (blockIdx.x < BB + 256) {
        int tid = (blockIdx.x - BB) * blockDim.x + threadIdx.x;
        int stride = 256 * blockDim.x;
        for (int i = tid; i < 512 * 128; i += stride) {
            g_wi0[i]             = wi0f[i];
            g_wi0[512 * 128 + i] = wi0b[i];
        }
        for (int i = tid; i < 512 * 256; i += stride) {
            g_wi1[i]             = wi1f[i];
            g_wi1[512 * 256 + i] = wi1b[i];
        }
        for (int i = tid; i < 512; i += stride) {
            g_b0[i]       = b0f[i];
            g_b0[512 + i] = b0b[i];
            g_b1[i]       = b1f[i];
            g_b1[512 + i] = b1b[i];
        }
        return;
    }

    // wh transpose: 32x32 tiles through smem, both sides coalesced
    __shared__ float ts[32][33];
    const float* whs[4] = { wh0f, wh0b, wh1f, wh1b };
    int tb   = blockIdx.x - (BB + 256);
    int dl   = tb >> 6;          // 0..3
    int tile = tb & 63;
    int r0 = (tile >> 2) * 32;   // row tile (512 rows / 32 = 16)
    int k0 = (tile & 3) * 32;    // k tile (128 / 32 = 4)
    const float* w = whs[dl];
    int tx = threadIdx.x & 31;
    int ty = threadIdx.x >> 5;   // 0..7
#pragma unroll
    for (int j = 0; j < 4; ++j)
        ts[ty + 8 * j][tx] = w[(r0 + ty + 8 * j) * 128 + k0 + tx];
    __syncthreads();
#pragma unroll
    for (int j = 0; j < 4; ++j)
        g_whT[dl * 65536 + (k0 + ty + 8 * j) * 512 + r0 + tx] = ts[tx][ty + 8 * j];
}

// ---------------- bf16 tensor-core GEMM, 32x32 warp tiles ----------------
// CTA tile 64m x 128n, 8 warps (2m x 4n), mma m16n8k16 bf16 fp32-accum.
__global__ void __launch_bounds__(256, 1) gemm_kernel(const float* __restrict__ Ain,
                                                      const int* __restrict__ gidx,
                                                      int Kd, int phase)
{
    extern __shared__ uint32_t gsm[];
    uint32_t* As = gsm;                // 64 x 68 words (packed bf16 pairs)
    uint32_t* Bs = gsm + 64 * 68;      // 128 x 68

    int m0 = blockIdx.y * 64;
    int n0 = blockIdx.x * 128;

    {
        int b  = m0 >> 9;
        int t0 = m0 & 511;
        if (t0 >= g_len[b]) return;   // uniform across CTA, before any barrier
    }

    const float* A    = phase ? g_H0  : Ain;
    const float* Bw   = phase ? g_wi1 : g_wi0;
    const float* bias = phase ? g_b1  : g_b0;

    int tid  = threadIdx.x;
    int w    = tid >> 5;
    int lane = tid & 31;
    int wm   = w & 1;           // 0..1 -> m sub-tile (32)
    int wn   = w >> 1;          // 0..3 -> n sub-tile (32)
    int g    = lane >> 2;       // 0..7
    int t    = lane & 3;        // 0..3

    // A loads: 64 rows, 4 threads per row
    int lrA = tid >> 2;
    int sfA = (tid & 3) * 32;   // float offset
    int swA = (tid & 3) * 16;   // word offset
    // B loads: 128 rows, 2 threads per row
    int lrB = tid >> 1;
    int sfB = (tid & 1) * 64;
    int swB = (tid & 1) * 32;

    size_t arow_idx = (size_t)(gidx ? gidx[m0 + lrA] : (m0 + lrA)) * Kd;
    size_t brow_idx = (size_t)(n0 + lrB) * Kd;

    float acc[2][4][4] = {};

    int nch = Kd >> 7;          // K chunks of 128
    for (int ch = 0; ch < nch; ++ch) {
        const float* arow = A  + arow_idx + ch * 128 + sfA;
        const float* brow = Bw + brow_idx + ch * 128 + sfB;
        __syncthreads();
#pragma unroll
        for (int i = 0; i < 8; ++i) {
            float4 av = *(const float4*)(arow + 4 * i);
            uint2 au = make_uint2(packbf2(make_float2(av.x, av.y)),
                                  packbf2(make_float2(av.z, av.w)));
            *(uint2*)&As[lrA * 68 + swA + 2 * i] = au;
        }
#pragma unroll
        for (int i = 0; i < 16; ++i) {
            float4 bv = *(const float4*)(brow + 4 * i);
            uint2 bu = make_uint2(packbf2(make_float2(bv.x, bv.y)),
                                  packbf2(make_float2(bv.z, bv.w)));
            *(uint2*)&Bs[lrB * 68 + swB + 2 * i] = bu;
        }
        __syncthreads();

#pragma unroll
        for (int ks = 0; ks < 8; ++ks) {
            int k0 = ks * 8 + t;
            uint32_t af[2][4];
#pragma unroll
            for (int mt = 0; mt < 2; ++mt) {
                const uint32_t* Ar0 = &As[(wm * 32 + mt * 16 + g)     * 68];
                const uint32_t* Ar1 = &As[(wm * 32 + mt * 16 + g + 8) * 68];
                af[mt][0] = Ar0[k0];
                af[mt][1] = Ar1[k0];
                af[mt][2] = Ar0[k0 + 4];
                af[mt][3] = Ar1[k0 + 4];
            }
#pragma unroll
            for (int nt = 0; nt < 4; ++nt) {
                const uint32_t* Br = &Bs[(wn * 32 + nt * 8 + g) * 68];
                uint32_t b0 = Br[k0];
                uint32_t b1 = Br[k0 + 4];
                mma_bf16(acc[0][nt], af[0][0], af[0][1], af[0][2], af[0][3], b0, b1);
                mma_bf16(acc[1][nt], af[1][0], af[1][1], af[1][2], af[1][3], b0, b1);
            }
        }
    }

#pragma unroll
    for (int mt = 0; mt < 2; ++mt) {
        int mr0 = m0 + wm * 32 + mt * 16 + g;
        int mr1 = mr0 + 8;
#pragma unroll
        for (int nt = 0; nt < 4; ++nt) {
            int nc = n0 + wn * 32 + nt * 8 + 2 * t;
            float2 bo = *(const float2*)&bias[nc];
            *(float2*)&g_G[(size_t)mr0 * 1024 + nc] =
                make_float2(acc[mt][nt][0] + bo.x, acc[mt][nt][1] + bo.y);
            *(float2*)&g_G[(size_t)mr1 * 1024 + nc] =
                make_float2(acc[mt][nt][2] + bo.x, acc[mt][nt][3] + bo.y);
        }
    }
}

// ---------------- LSTM recurrence (R9, measured best) ----------------
__device__ __forceinline__ float tanh_mufu(float x) {
    float r;
    asm("tanh.approx.f32 %0, %1;" : "=f"(r) : "f"(x));
    return r;
}
__device__ __forceinline__ float sigm(float x) {
    return fmaf(0.5f, tanh_mufu(0.5f * x), 0.5f);
}

__global__ void __launch_bounds__(256, 1) lstm_kernel(int layer)
{
    int b   = blockIdx.x;
    int dir = blockIdx.y;
    const float* whT = g_whT + (size_t)(layer * 2 + dir) * 65536;  // [k][512]

    extern __shared__ float sm[];
    uint32_t* pwsb = (uint32_t*)sm;                    // KS*256 u32: packed bf16 row-pairs
    float* zbuf  = sm + (KS * 512 * 2) / 4;            // 512
    float* hpair = zbuf + 512;                         // 128 float2 (h duplicated)

    int tid = threadIdx.x;

    for (int c = 0; c < KS / 4; ++c) {
        uint32_t v[4];
#pragma unroll
        for (int j = 0; j < 4; ++j) {
            float2 w = *(const float2*)&whT[(4 * c + j) * 512 + 2 * tid];
            v[j] = packbf2(w);
        }
        *(uint4*)&pwsb[(c * 256 + tid) * 4] = make_uint4(v[0], v[1], v[2], v[3]);
    }

    ull tw[TAILK];
#pragma unroll
    for (int j = 0; j < TAILK; ++j)
        tw[j] = *(const ull*)&whT[(KS + j) * 512 + 2 * tid];

    if (tid < 128) *(float2*)&hpair[2 * tid] = make_float2(0.f, 0.f);
    float c_st = 0.f;
    int len = g_len[b];
    float* Hout = layer ? g_H1 : g_H0;
    __syncthreads();

    const ulonglong2* hp = (const ulonglong2*)hpair;

    int t = (dir == 0) ? 0 : (len - 1);
    ull gc = *(const ull*)&g_G[((size_t)(b * TT + t)) * 1024 + dir * 512 + 2 * tid];

    for (int s = 0; s < len; ++s) {
        int sn = s + 1;
        int tnx;
        if (dir == 0) tnx = sn;
        else          tnx = len - 1 - sn;
        if (sn >= len) tnx = t;   // dummy (value unused on last iter)
        ull gn = *(const ull*)&g_G[((size_t)(b * TT + tnx)) * 1024 + dir * 512 + 2 * tid];

        ull acc0 = gc, acc1 = 0, acc2 = 0, acc3 = 0;
#pragma unroll
        for (int c = 0; c < KS / 4; ++c) {
            uint4 w4 = *(const uint4*)&pwsb[(c * 256 + tid) * 4];
            ulonglong2 hv0 = hp[2 * c];
            ulonglong2 hv1 = hp[2 * c + 1];
            acc0 = fma2(bf2up(w4.x), hv0.x, acc0);
            acc1 = fma2(bf2up(w4.y), hv0.y, acc1);
            acc2 = fma2(bf2up(w4.z), hv1.x, acc2);
            acc3 = fma2(bf2up(w4.w), hv1.y, acc3);
        }
#pragma unroll
        for (int j = 0; j < TAILK; j += 2) {
            ulonglong2 hv = hp[(KS + j) >> 1];
            acc0 = fma2(tw[j],     hv.x, acc0);
            acc1 = fma2(tw[j + 1], hv.y, acc1);
        }
        float2 z = unpack2(add2(add2(acc0, acc1), add2(acc2, acc3)));
        *(float2*)&zbuf[2 * tid] = z;
        __syncthreads();

        if (tid < 128) {
            float zi = zbuf[tid],       zf = zbuf[128 + tid];
            float zg = zbuf[256 + tid], zo = zbuf[384 + tid];
            c_st = sigm(zf) * c_st + sigm(zi) * tanh_mufu(zg);
            float h = sigm(zo) * tanh_mufu(c_st);
            *(float2*)&hpair[2 * tid] = make_float2(h, h);
            Hout[((size_t)(b * TT + t)) * 256 + dir * 128 + tid] = h;
        }
        __syncthreads();
        gc = gn;
        t  = tnx;
    }
}

// ---------------- emissions: e = H1 @ w_out^T + b_out (32 rows/CTA, length-clipped) ----------------
__global__ void emis_kernel(const float* __restrict__ w_out, const float* __restrict__ b_out)
{
    __shared__ float ws[32 * 257];
    __shared__ float hs[8][256];
    __shared__ float bs[32];

    int m0 = blockIdx.x * 32;
    {
        int b  = m0 >> 9;
        int t0 = m0 & 511;
        if (t0 >= g_len[b]) return;   // whole block padded; output never read
    }

    int tid = threadIdx.x;
    for (int i = tid; i < 32 * 256; i += 256)
        ws[(i >> 8) * 257 + (i & 255)] = w_out[i];
    if (tid < 32) bs[tid] = b_out[tid];

    int w    = tid >> 5;
    int lane = tid & 31;

    for (int rep = 0; rep < 4; ++rep) {
        int m = m0 + rep * 8 + w;
        for (int d = lane; d < 256; d += 32)
            hs[w][d] = g_H1[(size_t)m * 256 + d];
        __syncthreads();

        float e = bs[lane];
#pragma unroll 8
        for (int d = 0; d < 256; ++d)
            e += hs[w][d] * ws[lane * 257 + d];
        g_E[(size_t)m * 32 + lane] = e;
        __syncthreads();
    }
}

// ---------------- CRF: warp per batch, exp-space inner loop ----------------
__global__ void crf_kernel(const int* __restrict__ y, const float* __restrict__ trans,
                           float* __restrict__ out)
{
    int b    = blockIdx.x;
    int lane = threadIdx.x;
    __shared__ float tr[32 * 33];
    for (int i = lane; i < 1024; i += 32)
        tr[(i >> 5) * 33 + (i & 31)] = trans[i];
    __syncwarp();

    float etr[32];
#pragma unroll
    for (int k = 0; k < 32; ++k)
        etr[k] = __expf(tr[lane * 33 + k]);

    int len = g_len[b];
    const float* Eb = g_E + (size_t)b * TT * 32;

    float score = (lane == SOS) ? 0.f : -10000.f;
    for (int t = 0; t < len; ++t) {
        float e = Eb[t * 32 + lane];
        float m = score;
#pragma unroll
        for (int off = 16; off; off >>= 1)
            m = fmaxf(m, __shfl_xor_sync(0xffffffffu, m, off));
        float es = __expf(score - m);
        float s0 = 0.f, s1 = 0.f, s2 = 0.f, s3 = 0.f;
#pragma unroll
        for (int k = 0; k < 32; k += 4) {
            s0 = fmaf(etr[k],     __shfl_sync(0xffffffffu, es, k),     s0);
            s1 = fmaf(etr[k + 1], __shfl_sync(0xffffffffu, es, k + 1), s1);
            s2 = fmaf(etr[k + 2], __shfl_sync(0xffffffffu, es, k + 2), s2);
            s3 = fmaf(etr[k + 3], __shfl_sync(0xffffffffu, es, k + 3), s3);
        }
        score = e + m + __logf((s0 + s1) + (s2 + s3));
    }

    float v2 = score + tr[EOS * 33 + lane];
    float m = v2;
#pragma unroll
    for (int off = 16; off; off >>= 1) m = fmaxf(m, __shfl_xor_sync(0xffffffffu, m, off));
    float s = expf(v2 - m);
#pragma unroll
    for (int off = 16; off; off >>= 1) s += __shfl_xor_sync(0xffffffffu, s, off);
    float logZ = m + logf(s);

    const int* yb = y + b * (TT + 1);
    float g = 0.f;
    for (int t = lane; t < len; t += 32) {
        int y1 = yb[t + 1];
        int y0 = yb[t];
        g += Eb[t * 32 + y1] + tr[y1 * 33 + y0];
    }
#pragma unroll
    for (int off = 16; off; off >>= 1) g += __shfl_xor_sync(0xffffffffu, g, off);

    if (lane == 0) {
        g += tr[EOS * 33 + yb[len]];
        out[b] = logZ - g;
    }
}

// ---------------- launch ----------------
extern "C" void kernel_launch(void* const* d_in, const int* in_sizes, int n_in,
                              void* d_out, int out_size)
{
    const int*   x      = (const int*)  d_in[0];
    const int*   y      = (const int*)  d_in[1];
    const float* embed  = (const float*)d_in[2];
    const float* wi_l0f = (const float*)d_in[3];
    const float* wh_l0f = (const float*)d_in[4];
    const float* b_l0f  = (const float*)d_in[5];
    const float* wi_l0b = (const float*)d_in[6];
    const float* wh_l0b = (const float*)d_in[7];
    const float* b_l0b  = (const float*)d_in[8];
    const float* wi_l1f = (const float*)d_in[9];
    const float* wh_l1f = (const float*)d_in[10];
    const float* b_l1f  = (const float*)d_in[11];
    const float* wi_l1b = (const float*)d_in[12];
    const float* wh_l1b = (const float*)d_in[13];
    const float* b_l1b  = (const float*)d_in[14];
    const float* w_out  = (const float*)d_in[15];
    const float* b_out  = (const float*)d_in[16];
    const float* trans  = (const float*)d_in[17];
    float* out = (float*)d_out;

    cudaFuncSetAttribute(lstm_kernel, cudaFuncAttributeMaxDynamicSharedMemorySize, LSTM_SMEM);
    cudaFuncSetAttribute(gemm_kernel, cudaFuncAttributeMaxDynamicSharedMemorySize, GEMM_SMEM);

    prep_kernel<<<BB + 512, 256>>>(x,
                                   wi_l0f, wi_l0b, b_l0f, b_l0b,
                                   wi_l1f, wi_l1b, b_l1f, b_l1b,
                                   wh_l0f, wh_l0b, wh_l1f, wh_l1b);       // launch 1

    gemm_kernel<<<dim3(8, 512), 256, GEMM_SMEM>>>(embed, x, 128, 0);      // launch 2
    lstm_kernel<<<dim3(BB, 2), 256, LSTM_SMEM>>>(0);                      // launch 3

    gemm_kernel<<<dim3(8, 512), 256, GEMM_SMEM>>>(nullptr, nullptr, 256, 1); // launch 4
    lstm_kernel<<<dim3(BB, 2), 256, LSTM_SMEM>>>(1);                      // launch 5

    emis_kernel<<<(BB * TT) / 32, 256>>>(w_out, b_out);                   // launch 6
    crf_kernel<<<BB, 32>>>(y, trans, out);                                // launch 7
}